// round 1
// baseline (speedup 1.0000x reference)
#include <cuda_runtime.h>
#include <math.h>

// ---------------------------------------------------------------------------
// NeuralODE Tsit5 adaptive integrator, warp-per-trajectory.
// B=4096, D=64, HID=32, TRAJ_LEN=11, MAX_INNER=64.
// ---------------------------------------------------------------------------

#define DIM      64
#define HID      32
#define TRAJ_LEN 11
#define MAXI     64
#define WPB      4        // warps per block
#define TPB      (WPB*32)

// Tsit5 tableau (double-rounded to f32, identical to JAX f32 usage)
__device__ __constant__ float cA21 = (float)0.161;
__device__ __constant__ float cA31 = (float)-0.008480655492356989, cA32 = (float)0.335480655492357;
__device__ __constant__ float cA41 = (float)2.8971530571054935,  cA42 = (float)-6.359448489975075,  cA43 = (float)4.3622954328695815;
__device__ __constant__ float cA51 = (float)5.325864828439257,   cA52 = (float)-11.748883564062828, cA53 = (float)7.4955393428898365, cA54 = (float)-0.09249506636175525;
__device__ __constant__ float cA61 = (float)5.86145544294642,    cA62 = (float)-12.92096931784711,  cA63 = (float)8.159367898576159,  cA64 = (float)-0.071584973281401, cA65 = (float)-0.028269050394068383;
__device__ __constant__ float cB1  = (float)0.09646076681806523, cB2  = (float)0.01,                cB3  = (float)0.4798896504144996,
                              cB4  = (float)1.379008574103742,   cB5  = (float)-3.290069515436081,  cB6  = (float)2.324710524099774;
__device__ __constant__ float cE1  = (float)-0.00178001105222577714, cE2 = (float)-0.0008164344596567469, cE3 = (float)0.007880878010261995,
                              cE4  = (float)-0.1447110071732629,     cE5 = (float)0.5823571654525552,     cE6 = (float)-0.45808210592918697,
                              cE7  = (float)0.015151515151515152;

#define RTOL 1e-3f
#define ATOL 1e-6f

__device__ __forceinline__ float softplus_f(float x) {
    // jax.nn.softplus = logaddexp(x, 0) = max(x,0) + log1p(exp(-|x|))
    return fmaxf(x, 0.0f) + log1pf(expf(-fabsf(x)));
}

// One MLP eval: input z (distributed: lane has z[lane], z[lane+32]),
// output k (same distribution). Weights in registers, z/h broadcast via smem.
#define FEVAL(ZLO, ZHI, KLO, KHI) do {                                          \
    __syncwarp();                                                               \
    sy[lane] = (ZLO); sy[lane + 32] = (ZHI);                                    \
    __syncwarp();                                                               \
    {                                                                           \
        const float4* sy4 = (const float4*)sy;                                  \
        float a0 = 0.f, a1 = 0.f, a2 = 0.f, a3 = 0.f;                           \
        _Pragma("unroll")                                                       \
        for (int j = 0; j < 16; j++) {                                          \
            float4 v = sy4[j];                                                  \
            a0 = fmaf(w1[4*j+0], v.x, a0);                                      \
            a1 = fmaf(w1[4*j+1], v.y, a1);                                      \
            a2 = fmaf(w1[4*j+2], v.z, a2);                                      \
            a3 = fmaf(w1[4*j+3], v.w, a3);                                      \
        }                                                                       \
        float h1v = softplus_f(bb1 + ((a0 + a1) + (a2 + a3)));                  \
        __syncwarp();                                                           \
        sh[lane] = h1v;                                                         \
        __syncwarp();                                                           \
        const float4* sh4 = (const float4*)sh;                                  \
        a0 = a1 = a2 = a3 = 0.f;                                                \
        _Pragma("unroll")                                                       \
        for (int j = 0; j < 8; j++) {                                           \
            float4 v = sh4[j];                                                  \
            a0 = fmaf(w2[4*j+0], v.x, a0);                                      \
            a1 = fmaf(w2[4*j+1], v.y, a1);                                      \
            a2 = fmaf(w2[4*j+2], v.z, a2);                                      \
            a3 = fmaf(w2[4*j+3], v.w, a3);                                      \
        }                                                                       \
        float h2v = softplus_f(bb2 + ((a0 + a1) + (a2 + a3)));                  \
        __syncwarp();                                                           \
        sh[lane] = h2v;                                                         \
        __syncwarp();                                                           \
        float c0 = 0.f, c1 = 0.f, d0 = 0.f, d1 = 0.f;                           \
        _Pragma("unroll")                                                       \
        for (int j = 0; j < 8; j++) {                                           \
            float4 v = sh4[j];                                                  \
            c0 = fmaf(w3a[4*j+0], v.x, c0);                                     \
            c1 = fmaf(w3a[4*j+1], v.y, c1);                                     \
            c0 = fmaf(w3a[4*j+2], v.z, c0);                                     \
            c1 = fmaf(w3a[4*j+3], v.w, c1);                                     \
            d0 = fmaf(w3b[4*j+0], v.x, d0);                                     \
            d1 = fmaf(w3b[4*j+1], v.y, d1);                                     \
            d0 = fmaf(w3b[4*j+2], v.z, d0);                                     \
            d1 = fmaf(w3b[4*j+3], v.w, d1);                                     \
        }                                                                       \
        (KLO) = bb3a + (c0 + c1);                                               \
        (KHI) = bb3b + (d0 + d1);                                               \
    }                                                                           \
} while (0)

__global__ void __launch_bounds__(TPB)
ode_kernel(const float* __restrict__ x0s,
           const float* __restrict__ gW1, const float* __restrict__ gb1,
           const float* __restrict__ gW2, const float* __restrict__ gb2,
           const float* __restrict__ gW3, const float* __restrict__ gb3,
           const int*   __restrict__ Tp,
           float* __restrict__ out, int nTraj, int writeN)
{
    __shared__ __align__(16) float s_y[WPB][DIM];
    __shared__ __align__(16) float s_h[WPB][HID];

    const int wi   = threadIdx.x >> 5;
    const int lane = threadIdx.x & 31;
    const int traj = blockIdx.x * WPB + wi;
    if (traj >= nTraj) return;

    float* sy = s_y[wi];
    float* sh = s_h[wi];

    // Weights into registers: lane i owns W1 row i, W2 row i, W3 rows i and i+32.
    float w1[DIM], w2[HID], w3a[HID], w3b[HID];
    #pragma unroll
    for (int j = 0; j < DIM; j++) w1[j] = __ldg(gW1 + lane * DIM + j);
    #pragma unroll
    for (int j = 0; j < HID; j++) w2[j] = __ldg(gW2 + lane * HID + j);
    #pragma unroll
    for (int j = 0; j < HID; j++) {
        w3a[j] = __ldg(gW3 + lane * HID + j);
        w3b[j] = __ldg(gW3 + (lane + 32) * HID + j);
    }
    const float bb1  = __ldg(gb1 + lane);
    const float bb2  = __ldg(gb2 + lane);
    const float bb3a = __ldg(gb3 + lane);
    const float bb3b = __ldg(gb3 + lane + 32);

    float ylo = x0s[traj * DIM + lane];
    float yhi = x0s[traj * DIM + 32 + lane];

    float* orow = out + (size_t)traj * (TRAJ_LEN * DIM);
    orow[lane]      = ylo;
    orow[32 + lane] = yhi;

    const float Tf   = (float)__ldg(Tp);
    const float step = Tf / 10.0f;                 // linspace step (exact for T=10)
    float t  = 0.0f;
    float dt = 1e-3f;
    int   n  = 0;

    for (int iv = 1; iv < TRAJ_LEN; iv++) {
        const float t_target = step * (float)iv;

        for (int it = 0; it < MAXI; it++) {
            float remaining = t_target - t;
            if (remaining <= 1e-12f) break;        // 'done' state is frozen in the ref; exact early-exit
            n++;

            float h = fminf(dt, fmaxf(remaining, 0.0f));

            float k1lo, k1hi, k2lo, k2hi, k3lo, k3hi, k4lo, k4hi;
            float k5lo, k5hi, k6lo, k6hi, k7lo, k7hi;
            float zlo, zhi;

            FEVAL(ylo, yhi, k1lo, k1hi);

            zlo = fmaf(h, cA21 * k1lo, ylo);
            zhi = fmaf(h, cA21 * k1hi, yhi);
            FEVAL(zlo, zhi, k2lo, k2hi);

            zlo = fmaf(h, fmaf(cA32, k2lo, cA31 * k1lo), ylo);
            zhi = fmaf(h, fmaf(cA32, k2hi, cA31 * k1hi), yhi);
            FEVAL(zlo, zhi, k3lo, k3hi);

            zlo = fmaf(h, fmaf(cA43, k3lo, fmaf(cA42, k2lo, cA41 * k1lo)), ylo);
            zhi = fmaf(h, fmaf(cA43, k3hi, fmaf(cA42, k2hi, cA41 * k1hi)), yhi);
            FEVAL(zlo, zhi, k4lo, k4hi);

            zlo = fmaf(h, fmaf(cA54, k4lo, fmaf(cA53, k3lo, fmaf(cA52, k2lo, cA51 * k1lo))), ylo);
            zhi = fmaf(h, fmaf(cA54, k4hi, fmaf(cA53, k3hi, fmaf(cA52, k2hi, cA51 * k1hi))), yhi);
            FEVAL(zlo, zhi, k5lo, k5hi);

            zlo = fmaf(h, fmaf(cA65, k5lo, fmaf(cA64, k4lo, fmaf(cA63, k3lo, fmaf(cA62, k2lo, cA61 * k1lo)))), ylo);
            zhi = fmaf(h, fmaf(cA65, k5hi, fmaf(cA64, k4hi, fmaf(cA63, k3hi, fmaf(cA62, k2hi, cA61 * k1hi)))), yhi);
            FEVAL(zlo, zhi, k6lo, k6hi);

            float slo = fmaf(cB6, k6lo, fmaf(cB5, k5lo, fmaf(cB4, k4lo, fmaf(cB3, k3lo, fmaf(cB2, k2lo, cB1 * k1lo)))));
            float shi = fmaf(cB6, k6hi, fmaf(cB5, k5hi, fmaf(cB4, k4hi, fmaf(cB3, k3hi, fmaf(cB2, k2hi, cB1 * k1hi)))));
            float y5lo = fmaf(h, slo, ylo);
            float y5hi = fmaf(h, shi, yhi);

            FEVAL(y5lo, y5hi, k7lo, k7hi);

            float elo = h * fmaf(cE7, k7lo, fmaf(cE6, k6lo, fmaf(cE5, k5lo, fmaf(cE4, k4lo, fmaf(cE3, k3lo, fmaf(cE2, k2lo, cE1 * k1lo))))));
            float ehi = h * fmaf(cE7, k7hi, fmaf(cE6, k6hi, fmaf(cE5, k5hi, fmaf(cE4, k4hi, fmaf(cE3, k3hi, fmaf(cE2, k2hi, cE1 * k1hi))))));

            float sclo = fmaf(RTOL, fmaxf(fabsf(ylo), fabsf(y5lo)), ATOL);
            float schi = fmaf(RTOL, fmaxf(fabsf(yhi), fabsf(y5hi)), ATOL);
            float rlo = elo / sclo;
            float rhi = ehi / schi;
            float ss  = fmaf(rlo, rlo, rhi * rhi);
            #pragma unroll
            for (int o = 16; o; o >>= 1)
                ss += __shfl_xor_sync(0xffffffffu, ss, o);

            float enorm = fmaxf(sqrtf(ss * (1.0f / 64.0f)), 1e-10f);
            bool  accept = (enorm <= 1.0f);
            float fac = fminf(fmaxf(0.9f * powf(enorm, -0.2f), 0.1f), 5.0f);

            if (accept) { t = t + h; ylo = y5lo; yhi = y5hi; }
            dt = fmaxf(h * fac, 1e-8f);
        }

        orow[iv * DIM + lane]      = ylo;
        orow[iv * DIM + 32 + lane] = yhi;
    }

    // Sum of attempted-step counts across the batch (exact in f32: < 2^24)
    if (writeN && lane == 0)
        atomicAdd(out + (size_t)nTraj * TRAJ_LEN * DIM, (float)n);
}

extern "C" void kernel_launch(void* const* d_in, const int* in_sizes, int n_in,
                              void* d_out, int out_size)
{
    const float* x0s = (const float*)d_in[0];
    const float* W1  = (const float*)d_in[1];
    const float* b1  = (const float*)d_in[2];
    const float* W2  = (const float*)d_in[3];
    const float* b2  = (const float*)d_in[4];
    const float* W3  = (const float*)d_in[5];
    const float* b3  = (const float*)d_in[6];
    const int*   T   = (const int*)  d_in[7];
    float* out = (float*)d_out;

    const int nTraj = in_sizes[0] / DIM;
    const int trajElems = nTraj * TRAJ_LEN * DIM;
    const int writeN = (out_size > trajElems) ? 1 : 0;

    if (writeN) {
        // zero the step-count accumulator slot(s); graph-capturable memset node
        cudaMemsetAsync((char*)d_out + (size_t)trajElems * sizeof(float), 0,
                        (size_t)(out_size - trajElems) * sizeof(float), 0);
    }

    const int blocks = (nTraj + WPB - 1) / WPB;
    ode_kernel<<<blocks, TPB>>>(x0s, W1, b1, W2, b2, W3, b3, T, out, nTraj, writeN);
}

// round 2
// speedup vs baseline: 1.2625x; 1.2625x over previous
#include <cuda_runtime.h>
#include <math.h>

// ---------------------------------------------------------------------------
// NeuralODE Tsit5 adaptive integrator, warp-per-trajectory, f32x2-packed.
// Lane L owns state components (2L, 2L+1). B=4096, D=64, HID=32.
// ---------------------------------------------------------------------------

#define DIM      64
#define HID      32
#define TRAJ_LEN 11
#define MAXI     64
#define WPB      4
#define TPB      (WPB*32)

typedef unsigned long long u64;

// ---- packed f32x2 helpers (two independent fp32 ops; bit-identical to scalar) ----
__device__ __forceinline__ u64 pk2(float lo, float hi) {
    u64 r; asm("mov.b64 %0,{%1,%2};" : "=l"(r) : "f"(lo), "f"(hi)); return r;
}
__device__ __forceinline__ u64 pkb(float x) { return pk2(x, x); }
__device__ __forceinline__ void upk(u64 v, float& a, float& b) {
    asm("mov.b64 {%0,%1},%2;" : "=f"(a), "=f"(b) : "l"(v));
}
__device__ __forceinline__ u64 fma2(u64 a, u64 b, u64 c) {
    u64 d; asm("fma.rn.f32x2 %0,%1,%2,%3;" : "=l"(d) : "l"(a), "l"(b), "l"(c)); return d;
}
__device__ __forceinline__ u64 add2(u64 a, u64 b) {
    u64 d; asm("add.rn.f32x2 %0,%1,%2;" : "=l"(d) : "l"(a), "l"(b)); return d;
}
__device__ __forceinline__ u64 mul2(u64 a, u64 b) {
    u64 d; asm("mul.rn.f32x2 %0,%1,%2;" : "=l"(d) : "l"(a), "l"(b)); return d;
}
__device__ __forceinline__ float hsum2(u64 v) { float a, b; upk(v, a, b); return a + b; }

// Tsit5 tableau (f32, double-rounded same as JAX f32)
#define cA21 ((float)0.161)
#define cA31 ((float)-0.008480655492356989)
#define cA32 ((float)0.335480655492357)
#define cA41 ((float)2.8971530571054935)
#define cA42 ((float)-6.359448489975075)
#define cA43 ((float)4.3622954328695815)
#define cA51 ((float)5.325864828439257)
#define cA52 ((float)-11.748883564062828)
#define cA53 ((float)7.4955393428898365)
#define cA54 ((float)-0.09249506636175525)
#define cA61 ((float)5.86145544294642)
#define cA62 ((float)-12.92096931784711)
#define cA63 ((float)8.159367898576159)
#define cA64 ((float)-0.071584973281401)
#define cA65 ((float)-0.028269050394068383)
#define cB1  ((float)0.09646076681806523)
#define cB2  ((float)0.01)
#define cB3  ((float)0.4798896504144996)
#define cB4  ((float)1.379008574103742)
#define cB5  ((float)-3.290069515436081)
#define cB6  ((float)2.324710524099774)
#define cE1  ((float)-0.00178001105222577714)
#define cE2  ((float)-0.0008164344596567469)
#define cE3  ((float)0.007880878010261995)
#define cE4  ((float)-0.1447110071732629)
#define cE5  ((float)0.5823571654525552)
#define cE6  ((float)-0.45808210592918697)
#define cE7  ((float)0.015151515151515152)

#define RTOL 1e-3f
#define ATOL 1e-6f

__device__ __forceinline__ float softplus_f(float x) {
    // max(x,0) + log1p(exp(-|x|)); __expf ~2ulp, log1pf accurate
    return fmaxf(x, 0.0f) + log1pf(__expf(-fabsf(x)));
}

// Broadcast with ping-pong buffers: exactly ONE syncwarp per broadcast.
// Safe: reads of buffer X always precede (program order) the write+sync of the
// NEXT broadcast (buffer Y); by the time any lane rewrites X, all lanes have
// passed the Y-sync and therefore finished their X-reads.
#define BCAST64(ZP) do { bsel ^= 1; float* _b = bsel ? bufA : bufB;            \
    ((u64*)_b)[lane] = (ZP); __syncwarp(); cur = _b; } while (0)
#define BCAST32(HV) do { bsel ^= 1; float* _b = bsel ? bufA : bufB;            \
    _b[lane] = (HV); __syncwarp(); cur = _b; } while (0)

// One MLP eval. Input/output pairs packed (comp 2L, 2L+1).
#define FEVAL(ZP, KP) do {                                                     \
    BCAST64(ZP);                                                               \
    { const ulonglong2* _z = (const ulonglong2*)cur;                           \
      u64 a0 = 0, a1 = 0, a2 = 0, a3 = 0;                                      \
      _Pragma("unroll")                                                        \
      for (int j = 0; j < 8; j++) {                                            \
          ulonglong2 qa = _z[2*j], qb = _z[2*j+1];                             \
          a0 = fma2(w1p[4*j+0], qa.x, a0);                                     \
          a1 = fma2(w1p[4*j+1], qa.y, a1);                                     \
          a2 = fma2(w1p[4*j+2], qb.x, a2);                                     \
          a3 = fma2(w1p[4*j+3], qb.y, a3);                                     \
      }                                                                        \
      float h1v = softplus_f(hsum2(add2(add2(a0,a1), add2(a2,a3))) + bb1);     \
      BCAST32(h1v);                                                            \
      const ulonglong2* _h = (const ulonglong2*)cur;                           \
      a0 = a1 = a2 = a3 = 0;                                                   \
      _Pragma("unroll")                                                        \
      for (int j = 0; j < 4; j++) {                                            \
          ulonglong2 qa = _h[2*j], qb = _h[2*j+1];                             \
          a0 = fma2(w2p[4*j+0], qa.x, a0);                                     \
          a1 = fma2(w2p[4*j+1], qa.y, a1);                                     \
          a2 = fma2(w2p[4*j+2], qb.x, a2);                                     \
          a3 = fma2(w2p[4*j+3], qb.y, a3);                                     \
      }                                                                        \
      float h2v = softplus_f(hsum2(add2(add2(a0,a1), add2(a2,a3))) + bb2);     \
      BCAST32(h2v);                                                            \
      const ulonglong2* _g = (const ulonglong2*)cur;                           \
      u64 c0 = 0, c1 = 0, d0 = 0, d1 = 0;                                      \
      _Pragma("unroll")                                                        \
      for (int j = 0; j < 4; j++) {                                            \
          ulonglong2 qa = _g[2*j], qb = _g[2*j+1];                             \
          c0 = fma2(w3p0[4*j+0], qa.x, c0);                                    \
          c1 = fma2(w3p0[4*j+1], qa.y, c1);                                    \
          c0 = fma2(w3p0[4*j+2], qb.x, c0);                                    \
          c1 = fma2(w3p0[4*j+3], qb.y, c1);                                    \
          d0 = fma2(w3p1[4*j+0], qa.x, d0);                                    \
          d1 = fma2(w3p1[4*j+1], qa.y, d1);                                    \
          d0 = fma2(w3p1[4*j+2], qb.x, d0);                                    \
          d1 = fma2(w3p1[4*j+3], qb.y, d1);                                    \
      }                                                                        \
      float kx = hsum2(add2(c0, c1)) + b3x;                                    \
      float ky = hsum2(add2(d0, d1)) + b3y;                                    \
      (KP) = pk2(kx, ky);                                                      \
    } } while (0)

__global__ void __launch_bounds__(TPB)
ode_kernel(const float* __restrict__ x0s,
           const float* __restrict__ gW1, const float* __restrict__ gb1,
           const float* __restrict__ gW2, const float* __restrict__ gb2,
           const float* __restrict__ gW3, const float* __restrict__ gb3,
           const int*   __restrict__ Tp,
           float* __restrict__ out, int nTraj, int writeN)
{
    __shared__ __align__(16) float s_bufA[WPB][DIM];
    __shared__ __align__(16) float s_bufB[WPB][DIM];

    const int wi   = threadIdx.x >> 5;
    const int lane = threadIdx.x & 31;
    const int traj = blockIdx.x * WPB + wi;
    if (traj >= nTraj) return;

    float* bufA = s_bufA[wi];
    float* bufB = s_bufB[wi];
    int bsel = 0;
    const float* cur = bufA;

    // Weights, packed: lane owns W1 row L, W2 row L, W3 rows 2L and 2L+1.
    u64 w1p[32], w2p[16], w3p0[16], w3p1[16];
    {
        const u64* r1 = (const u64*)(gW1 + lane * DIM);
        #pragma unroll
        for (int j = 0; j < 32; j++) w1p[j] = __ldg(r1 + j);
        const u64* r2 = (const u64*)(gW2 + lane * HID);
        #pragma unroll
        for (int j = 0; j < 16; j++) w2p[j] = __ldg(r2 + j);
        const u64* r3a = (const u64*)(gW3 + (2*lane)   * HID);
        const u64* r3b = (const u64*)(gW3 + (2*lane+1) * HID);
        #pragma unroll
        for (int j = 0; j < 16; j++) { w3p0[j] = __ldg(r3a + j); w3p1[j] = __ldg(r3b + j); }
    }
    const float bb1 = __ldg(gb1 + lane);
    const float bb2 = __ldg(gb2 + lane);
    const float b3x = __ldg(gb3 + 2*lane);
    const float b3y = __ldg(gb3 + 2*lane + 1);

    // State: packed pair (y[2L], y[2L+1])
    u64 y = ((const u64*)(x0s + (size_t)traj * DIM))[lane];

    float* orow = out + (size_t)traj * (TRAJ_LEN * DIM);
    ((u64*)orow)[lane] = y;

    const float Tf   = (float)__ldg(Tp);
    const float step = Tf / 10.0f;
    float t  = 0.0f;
    float dt = 1e-3f;
    int   n  = 0;

    for (int iv = 1; iv < TRAJ_LEN; iv++) {
        const float t_target = step * (float)iv;

        for (int it = 0; it < MAXI; it++) {
            float remaining = t_target - t;
            if (remaining <= 1e-12f) break;   // ref freezes state when done: exact early-exit
            n++;

            float h = fminf(dt, fmaxf(remaining, 0.0f));

            u64 k1, k2, k3, k4, k5, k6, k7, z;

            FEVAL(y, k1);

            z = fma2(pkb(h*cA21), k1, y);
            FEVAL(z, k2);

            z = fma2(pkb(h*cA31), k1, fma2(pkb(h*cA32), k2, y));
            FEVAL(z, k3);

            z = fma2(pkb(h*cA41), k1, fma2(pkb(h*cA42), k2, fma2(pkb(h*cA43), k3, y)));
            FEVAL(z, k4);

            z = fma2(pkb(h*cA51), k1, fma2(pkb(h*cA52), k2, fma2(pkb(h*cA53), k3,
                fma2(pkb(h*cA54), k4, y))));
            FEVAL(z, k5);

            z = fma2(pkb(h*cA61), k1, fma2(pkb(h*cA62), k2, fma2(pkb(h*cA63), k3,
                fma2(pkb(h*cA64), k4, fma2(pkb(h*cA65), k5, y)))));
            FEVAL(z, k6);

            u64 y5 = fma2(pkb(h*cB1), k1, fma2(pkb(h*cB2), k2, fma2(pkb(h*cB3), k3,
                     fma2(pkb(h*cB4), k4, fma2(pkb(h*cB5), k5, fma2(pkb(h*cB6), k6, y))))));

            FEVAL(y5, k7);

            u64 err = fma2(pkb(h*cE1), k1, fma2(pkb(h*cE2), k2, fma2(pkb(h*cE3), k3,
                      fma2(pkb(h*cE4), k4, fma2(pkb(h*cE5), k5, fma2(pkb(h*cE6), k6,
                      mul2(pkb(h*cE7), k7)))))));

            float ylo, yhi, y5lo, y5hi, elo, ehi;
            upk(y, ylo, yhi); upk(y5, y5lo, y5hi); upk(err, elo, ehi);

            float sclo = fmaf(RTOL, fmaxf(fabsf(ylo), fabsf(y5lo)), ATOL);
            float schi = fmaf(RTOL, fmaxf(fabsf(yhi), fabsf(y5hi)), ATOL);
            float rlo = __fdividef(elo, sclo);
            float rhi = __fdividef(ehi, schi);
            float ss  = fmaf(rlo, rlo, rhi * rhi);
            #pragma unroll
            for (int o = 16; o; o >>= 1)
                ss += __shfl_xor_sync(0xffffffffu, ss, o);

            float enorm = fmaxf(sqrtf(ss * 0.015625f), 1e-10f);
            bool  accept = (enorm <= 1.0f);
            float fac = fminf(fmaxf(0.9f * __powf(enorm, -0.2f), 0.1f), 5.0f);

            if (accept) { t = t + h; y = y5; }
            dt = fmaxf(h * fac, 1e-8f);
        }

        ((u64*)(orow + iv * DIM))[lane] = y;
    }

    if (writeN && lane == 0)
        atomicAdd(out + (size_t)nTraj * TRAJ_LEN * DIM, (float)n);
}

extern "C" void kernel_launch(void* const* d_in, const int* in_sizes, int n_in,
                              void* d_out, int out_size)
{
    const float* x0s = (const float*)d_in[0];
    const float* W1  = (const float*)d_in[1];
    const float* b1  = (const float*)d_in[2];
    const float* W2  = (const float*)d_in[3];
    const float* b2  = (const float*)d_in[4];
    const float* W3  = (const float*)d_in[5];
    const float* b3  = (const float*)d_in[6];
    const int*   T   = (const int*)  d_in[7];
    float* out = (float*)d_out;

    const int nTraj = in_sizes[0] / DIM;
    const int trajElems = nTraj * TRAJ_LEN * DIM;
    const int writeN = (out_size > trajElems) ? 1 : 0;

    if (writeN) {
        cudaMemsetAsync((char*)d_out + (size_t)trajElems * sizeof(float), 0,
                        (size_t)(out_size - trajElems) * sizeof(float), 0);
    }

    const int blocks = (nTraj + WPB - 1) / WPB;
    ode_kernel<<<blocks, TPB>>>(x0s, W1, b1, W2, b2, W3, b3, T, out, nTraj, writeN);
}

// round 3
// speedup vs baseline: 1.2933x; 1.0244x over previous
#include <cuda_runtime.h>
#include <math.h>

// ---------------------------------------------------------------------------
// NeuralODE Tsit5 adaptive integrator, warp-per-trajectory, f32x2-packed,
// shfl-broadcast hidden layers. Lane L owns components (2L, 2L+1).
// ---------------------------------------------------------------------------

#define DIM      64
#define HID      32
#define TRAJ_LEN 11
#define MAXI     64
#define WPB      4
#define TPB      (WPB*32)

typedef unsigned long long u64;

__device__ __forceinline__ u64 pk2(float lo, float hi) {
    u64 r; asm("mov.b64 %0,{%1,%2};" : "=l"(r) : "f"(lo), "f"(hi)); return r;
}
__device__ __forceinline__ u64 pkb(float x) { return pk2(x, x); }
__device__ __forceinline__ void upk(u64 v, float& a, float& b) {
    asm("mov.b64 {%0,%1},%2;" : "=f"(a), "=f"(b) : "l"(v));
}
__device__ __forceinline__ u64 fma2(u64 a, u64 b, u64 c) {
    u64 d; asm("fma.rn.f32x2 %0,%1,%2,%3;" : "=l"(d) : "l"(a), "l"(b), "l"(c)); return d;
}
__device__ __forceinline__ u64 add2(u64 a, u64 b) {
    u64 d; asm("add.rn.f32x2 %0,%1,%2;" : "=l"(d) : "l"(a), "l"(b)); return d;
}
__device__ __forceinline__ u64 mul2(u64 a, u64 b) {
    u64 d; asm("mul.rn.f32x2 %0,%1,%2;" : "=l"(d) : "l"(a), "l"(b)); return d;
}
__device__ __forceinline__ float hsum2(u64 v) { float a, b; upk(v, a, b); return a + b; }

// Broadcast lanes (2k, 2k+1) of v as a packed pair
__device__ __forceinline__ u64 bpair(float v, int k) {
    float a = __shfl_sync(0xffffffffu, v, 2*k);
    float b = __shfl_sync(0xffffffffu, v, 2*k + 1);
    return pk2(a, b);
}

// Tsit5 tableau (f32)
#define cA21 ((float)0.161)
#define cA31 ((float)-0.008480655492356989)
#define cA32 ((float)0.335480655492357)
#define cA41 ((float)2.8971530571054935)
#define cA42 ((float)-6.359448489975075)
#define cA43 ((float)4.3622954328695815)
#define cA51 ((float)5.325864828439257)
#define cA52 ((float)-11.748883564062828)
#define cA53 ((float)7.4955393428898365)
#define cA54 ((float)-0.09249506636175525)
#define cA61 ((float)5.86145544294642)
#define cA62 ((float)-12.92096931784711)
#define cA63 ((float)8.159367898576159)
#define cA64 ((float)-0.071584973281401)
#define cA65 ((float)-0.028269050394068383)
#define cB1  ((float)0.09646076681806523)
#define cB2  ((float)0.01)
#define cB3  ((float)0.4798896504144996)
#define cB4  ((float)1.379008574103742)
#define cB5  ((float)-3.290069515436081)
#define cB6  ((float)2.324710524099774)
#define cE1  ((float)-0.00178001105222577714)
#define cE2  ((float)-0.0008164344596567469)
#define cE3  ((float)0.007880878010261995)
#define cE4  ((float)-0.1447110071732629)
#define cE5  ((float)0.5823571654525552)
#define cE6  ((float)-0.45808210592918697)
#define cE7  ((float)0.015151515151515152)

#define RTOL 1e-3f
#define ATOL 1e-6f

__device__ __forceinline__ float softplus_f(float x) {
    // max(x,0) + log(1 + exp(-|x|)); e in (0,1], fast MUFU path. abs err ~4e-8.
    return fmaxf(x, 0.0f) + __logf(1.0f + __expf(-fabsf(x)));
}

// One MLP eval; input/output packed pairs (2L, 2L+1).
// mv1 via smem broadcast (64-wide input), mv2/mv3 via warp shuffles.
#define FEVAL(ZP, KP) do {                                                     \
    bsel ^= 1; float* _b = bsel ? bufA : bufB;                                 \
    ((u64*)_b)[lane] = (ZP);                                                   \
    __syncwarp();                                                              \
    { const ulonglong2* _z = (const ulonglong2*)_b;                            \
      u64 a0=0,a1=0,a2=0,a3=0,a4=0,a5=0,a6=0,a7=0;                             \
      _Pragma("unroll")                                                        \
      for (int j = 0; j < 4; j++) {                                            \
          ulonglong2 q0 = _z[4*j+0], q1 = _z[4*j+1];                           \
          ulonglong2 q2 = _z[4*j+2], q3 = _z[4*j+3];                           \
          a0 = fma2(w1p[8*j+0], q0.x, a0);                                     \
          a1 = fma2(w1p[8*j+1], q0.y, a1);                                     \
          a2 = fma2(w1p[8*j+2], q1.x, a2);                                     \
          a3 = fma2(w1p[8*j+3], q1.y, a3);                                     \
          a4 = fma2(w1p[8*j+4], q2.x, a4);                                     \
          a5 = fma2(w1p[8*j+5], q2.y, a5);                                     \
          a6 = fma2(w1p[8*j+6], q3.x, a6);                                     \
          a7 = fma2(w1p[8*j+7], q3.y, a7);                                     \
      }                                                                        \
      u64 s = add2(add2(add2(a0,a1), add2(a2,a3)),                             \
                   add2(add2(a4,a5), add2(a6,a7)));                            \
      float h1v = softplus_f(hsum2(s) + bb1);                                  \
      /* layer 2: 32x32, h1 one value per lane, shfl broadcast */              \
      u64 b0=0,b1=0,b2=0,b3=0;                                                 \
      _Pragma("unroll")                                                        \
      for (int k = 0; k < 16; k += 4) {                                        \
          b0 = fma2(w2p[k+0], bpair(h1v, k+0), b0);                            \
          b1 = fma2(w2p[k+1], bpair(h1v, k+1), b1);                            \
          b2 = fma2(w2p[k+2], bpair(h1v, k+2), b2);                            \
          b3 = fma2(w2p[k+3], bpair(h1v, k+3), b3);                            \
      }                                                                        \
      float h2v = softplus_f(hsum2(add2(add2(b0,b1), add2(b2,b3))) + bb2);     \
      /* layer 3: 64x32, two output rows per lane */                           \
      u64 c0=0,c1=0,d0=0,d1=0;                                                 \
      _Pragma("unroll")                                                        \
      for (int k = 0; k < 16; k += 2) {                                        \
          u64 v0 = bpair(h2v, k), v1 = bpair(h2v, k+1);                        \
          c0 = fma2(w3p0[k],   v0, c0);  d0 = fma2(w3p1[k],   v0, d0);         \
          c1 = fma2(w3p0[k+1], v1, c1);  d1 = fma2(w3p1[k+1], v1, d1);         \
      }                                                                        \
      float kx = hsum2(add2(c0, c1)) + b3x;                                    \
      float ky = hsum2(add2(d0, d1)) + b3y;                                    \
      (KP) = pk2(kx, ky);                                                      \
    } } while (0)

__global__ void __launch_bounds__(TPB)
ode_kernel(const float* __restrict__ x0s,
           const float* __restrict__ gW1, const float* __restrict__ gb1,
           const float* __restrict__ gW2, const float* __restrict__ gb2,
           const float* __restrict__ gW3, const float* __restrict__ gb3,
           const int*   __restrict__ Tp,
           float* __restrict__ out, int nTraj, int writeN)
{
    __shared__ __align__(16) float s_bufA[WPB][DIM];
    __shared__ __align__(16) float s_bufB[WPB][DIM];

    const int wi   = threadIdx.x >> 5;
    const int lane = threadIdx.x & 31;
    const int traj = blockIdx.x * WPB + wi;
    if (traj >= nTraj) return;

    float* bufA = s_bufA[wi];
    float* bufB = s_bufB[wi];
    int bsel = 0;

    // Weights: lane owns W1 row L, W2 row L, W3 rows 2L and 2L+1 (packed pairs).
    u64 w1p[32], w2p[16], w3p0[16], w3p1[16];
    {
        const u64* r1 = (const u64*)(gW1 + lane * DIM);
        #pragma unroll
        for (int j = 0; j < 32; j++) w1p[j] = __ldg(r1 + j);
        const u64* r2 = (const u64*)(gW2 + lane * HID);
        #pragma unroll
        for (int j = 0; j < 16; j++) w2p[j] = __ldg(r2 + j);
        const u64* r3a = (const u64*)(gW3 + (2*lane)   * HID);
        const u64* r3b = (const u64*)(gW3 + (2*lane+1) * HID);
        #pragma unroll
        for (int j = 0; j < 16; j++) { w3p0[j] = __ldg(r3a + j); w3p1[j] = __ldg(r3b + j); }
    }
    const float bb1 = __ldg(gb1 + lane);
    const float bb2 = __ldg(gb2 + lane);
    const float b3x = __ldg(gb3 + 2*lane);
    const float b3y = __ldg(gb3 + 2*lane + 1);

    u64 y = ((const u64*)(x0s + (size_t)traj * DIM))[lane];

    float* orow = out + (size_t)traj * (TRAJ_LEN * DIM);
    ((u64*)orow)[lane] = y;

    const float Tf   = (float)__ldg(Tp);
    const float step = Tf / 10.0f;
    float t  = 0.0f;
    float dt = 1e-3f;
    int   n  = 0;

    for (int iv = 1; iv < TRAJ_LEN; iv++) {
        const float t_target = step * (float)iv;

        for (int it = 0; it < MAXI; it++) {
            float remaining = t_target - t;
            if (remaining <= 1e-12f) break;   // ref freezes state when done: exact early-exit
            n++;

            float h = fminf(dt, fmaxf(remaining, 0.0f));

            u64 k1, k2, k3, k4, k5, k6, k7, z;

            FEVAL(y, k1);

            z = fma2(pkb(h*cA21), k1, y);
            FEVAL(z, k2);

            z = fma2(pkb(h*cA31), k1, fma2(pkb(h*cA32), k2, y));
            FEVAL(z, k3);

            z = fma2(pkb(h*cA41), k1, fma2(pkb(h*cA42), k2, fma2(pkb(h*cA43), k3, y)));
            FEVAL(z, k4);

            z = fma2(pkb(h*cA51), k1, fma2(pkb(h*cA52), k2, fma2(pkb(h*cA53), k3,
                fma2(pkb(h*cA54), k4, y))));
            FEVAL(z, k5);

            z = fma2(pkb(h*cA61), k1, fma2(pkb(h*cA62), k2, fma2(pkb(h*cA63), k3,
                fma2(pkb(h*cA64), k4, fma2(pkb(h*cA65), k5, y)))));
            FEVAL(z, k6);

            u64 y5 = fma2(pkb(h*cB1), k1, fma2(pkb(h*cB2), k2, fma2(pkb(h*cB3), k3,
                     fma2(pkb(h*cB4), k4, fma2(pkb(h*cB5), k5, fma2(pkb(h*cB6), k6, y))))));

            FEVAL(y5, k7);

            u64 err = fma2(pkb(h*cE1), k1, fma2(pkb(h*cE2), k2, fma2(pkb(h*cE3), k3,
                      fma2(pkb(h*cE4), k4, fma2(pkb(h*cE5), k5, fma2(pkb(h*cE6), k6,
                      mul2(pkb(h*cE7), k7)))))));

            float ylo, yhi, y5lo, y5hi, elo, ehi;
            upk(y, ylo, yhi); upk(y5, y5lo, y5hi); upk(err, elo, ehi);

            float sclo = fmaf(RTOL, fmaxf(fabsf(ylo), fabsf(y5lo)), ATOL);
            float schi = fmaf(RTOL, fmaxf(fabsf(yhi), fabsf(y5hi)), ATOL);
            float rlo = __fdividef(elo, sclo);
            float rhi = __fdividef(ehi, schi);
            float ss  = fmaf(rlo, rlo, rhi * rhi);
            #pragma unroll
            for (int o = 16; o; o >>= 1)
                ss += __shfl_xor_sync(0xffffffffu, ss, o);

            // accept: enorm = max(sqrt(ss/64),1e-10) <= 1  <=>  ss <= 64 (sqrt monotone)
            bool accept = (ss <= 64.0f);
            // fac = clip(0.9*enorm^-0.2, 0.1, 5) ; enorm^-0.2 = (ss/64)^-0.1
            float q   = fmaxf(ss * 0.015625f, 1e-20f);
            float fac = fminf(fmaxf(0.9f * __powf(q, -0.1f), 0.1f), 5.0f);

            if (accept) { t = t + h; y = y5; }
            dt = fmaxf(h * fac, 1e-8f);
        }

        ((u64*)(orow + iv * DIM))[lane] = y;
    }

    if (writeN && lane == 0)
        atomicAdd(out + (size_t)nTraj * TRAJ_LEN * DIM, (float)n);
}

extern "C" void kernel_launch(void* const* d_in, const int* in_sizes, int n_in,
                              void* d_out, int out_size)
{
    const float* x0s = (const float*)d_in[0];
    const float* W1  = (const float*)d_in[1];
    const float* b1  = (const float*)d_in[2];
    const float* W2  = (const float*)d_in[3];
    const float* b2  = (const float*)d_in[4];
    const float* W3  = (const float*)d_in[5];
    const float* b3  = (const float*)d_in[6];
    const int*   T   = (const int*)  d_in[7];
    float* out = (float*)d_out;

    const int nTraj = in_sizes[0] / DIM;
    const int trajElems = nTraj * TRAJ_LEN * DIM;
    const int writeN = (out_size > trajElems) ? 1 : 0;

    if (writeN) {
        cudaMemsetAsync((char*)d_out + (size_t)trajElems * sizeof(float), 0,
                        (size_t)(out_size - trajElems) * sizeof(float), 0);
    }

    const int blocks = (nTraj + WPB - 1) / WPB;
    ode_kernel<<<blocks, TPB>>>(x0s, W1, b1, W2, b2, W3, b3, T, out, nTraj, writeN);
}

// round 6
// speedup vs baseline: 1.6388x; 1.2672x over previous
#include <cuda_runtime.h>
#include <math.h>

// ---------------------------------------------------------------------------
// NeuralODE Tsit5 adaptive integrator, warp-per-trajectory, f32x2-packed,
// FSAL k1 reuse, LDS ping-pong broadcasts, shfl-butterfly error norm.
// Lane L owns state components (2L, 2L+1). B=4096, D=64, HID=32.
// ---------------------------------------------------------------------------

#define DIM      64
#define HID      32
#define TRAJ_LEN 11
#define MAXI     64
#define WPB      4
#define TPB      (WPB*32)

typedef unsigned long long u64;

__device__ __forceinline__ u64 pk2(float lo, float hi) {
    u64 r; asm("mov.b64 %0,{%1,%2};" : "=l"(r) : "f"(lo), "f"(hi)); return r;
}
__device__ __forceinline__ u64 pkb(float x) { return pk2(x, x); }
__device__ __forceinline__ void upk(u64 v, float& a, float& b) {
    asm("mov.b64 {%0,%1},%2;" : "=f"(a), "=f"(b) : "l"(v));
}
__device__ __forceinline__ u64 fma2(u64 a, u64 b, u64 c) {
    u64 d; asm("fma.rn.f32x2 %0,%1,%2,%3;" : "=l"(d) : "l"(a), "l"(b), "l"(c)); return d;
}
__device__ __forceinline__ u64 add2(u64 a, u64 b) {
    u64 d; asm("add.rn.f32x2 %0,%1,%2;" : "=l"(d) : "l"(a), "l"(b)); return d;
}
__device__ __forceinline__ u64 mul2(u64 a, u64 b) {
    u64 d; asm("mul.rn.f32x2 %0,%1,%2;" : "=l"(d) : "l"(a), "l"(b)); return d;
}
__device__ __forceinline__ float hsum2(u64 v) { float a, b; upk(v, a, b); return a + b; }

// Tsit5 tableau (f32)
#define cA21 ((float)0.161)
#define cA31 ((float)-0.008480655492356989)
#define cA32 ((float)0.335480655492357)
#define cA41 ((float)2.8971530571054935)
#define cA42 ((float)-6.359448489975075)
#define cA43 ((float)4.3622954328695815)
#define cA51 ((float)5.325864828439257)
#define cA52 ((float)-11.748883564062828)
#define cA53 ((float)7.4955393428898365)
#define cA54 ((float)-0.09249506636175525)
#define cA61 ((float)5.86145544294642)
#define cA62 ((float)-12.92096931784711)
#define cA63 ((float)8.159367898576159)
#define cA64 ((float)-0.071584973281401)
#define cA65 ((float)-0.028269050394068383)
#define cB1  ((float)0.09646076681806523)
#define cB2  ((float)0.01)
#define cB3  ((float)0.4798896504144996)
#define cB4  ((float)1.379008574103742)
#define cB5  ((float)-3.290069515436081)
#define cB6  ((float)2.324710524099774)
#define cE1  ((float)-0.00178001105222577714)
#define cE2  ((float)-0.0008164344596567469)
#define cE3  ((float)0.007880878010261995)
#define cE4  ((float)-0.1447110071732629)
#define cE5  ((float)0.5823571654525552)
#define cE6  ((float)-0.45808210592918697)
#define cE7  ((float)0.015151515151515152)

#define RTOL 1e-3f
#define ATOL 1e-6f

__device__ __forceinline__ float softplus_f(float x) {
    // max(x,0) + log(1 + exp(-|x|)); e in (0,1], fast MUFU path. abs err ~4e-8.
    return fmaxf(x, 0.0f) + __logf(1.0f + __expf(-fabsf(x)));
}

// Ping-pong smem broadcast, ONE syncwarp each. Buffer X is rewritten only two
// broadcasts later; the intervening syncwarp guarantees all lanes' reads of X
// (which precede their arrival at that sync) are complete.
#define BCAST64(ZP) do { bsel ^= 1; float* _b = bsel ? bufA : bufB;            \
    ((u64*)_b)[lane] = (ZP); __syncwarp(); cur = _b; } while (0)
#define BCAST32(HV) do { bsel ^= 1; float* _b = bsel ? bufA : bufB;            \
    _b[lane] = (HV); __syncwarp(); cur = _b; } while (0)

// One MLP eval; input/output packed pairs (2L, 2L+1). All broadcasts via LDS.
#define FEVAL(ZP, KP) do {                                                     \
    BCAST64(ZP);                                                               \
    { const ulonglong2* _z = (const ulonglong2*)cur;                           \
      u64 a0=0,a1=0,a2=0,a3=0,a4=0,a5=0,a6=0,a7=0;                             \
      _Pragma("unroll")                                                        \
      for (int j = 0; j < 4; j++) {                                            \
          ulonglong2 q0 = _z[4*j+0], q1 = _z[4*j+1];                           \
          ulonglong2 q2 = _z[4*j+2], q3 = _z[4*j+3];                           \
          a0 = fma2(w1p[8*j+0], q0.x, a0);                                     \
          a1 = fma2(w1p[8*j+1], q0.y, a1);                                     \
          a2 = fma2(w1p[8*j+2], q1.x, a2);                                     \
          a3 = fma2(w1p[8*j+3], q1.y, a3);                                     \
          a4 = fma2(w1p[8*j+4], q2.x, a4);                                     \
          a5 = fma2(w1p[8*j+5], q2.y, a5);                                     \
          a6 = fma2(w1p[8*j+6], q3.x, a6);                                     \
          a7 = fma2(w1p[8*j+7], q3.y, a7);                                     \
      }                                                                        \
      u64 s = add2(add2(add2(a0,a1), add2(a2,a3)),                             \
                   add2(add2(a4,a5), add2(a6,a7)));                            \
      float h1v = softplus_f(hsum2(s) + bb1);                                  \
      BCAST32(h1v);                                                            \
      const ulonglong2* _h = (const ulonglong2*)cur;                           \
      u64 b0=0,b1=0,b2=0,b3=0;                                                 \
      _Pragma("unroll")                                                        \
      for (int j = 0; j < 4; j++) {                                            \
          ulonglong2 qa = _h[2*j], qb = _h[2*j+1];                             \
          b0 = fma2(w2p[4*j+0], qa.x, b0);                                     \
          b1 = fma2(w2p[4*j+1], qa.y, b1);                                     \
          b2 = fma2(w2p[4*j+2], qb.x, b2);                                     \
          b3 = fma2(w2p[4*j+3], qb.y, b3);                                     \
      }                                                                        \
      float h2v = softplus_f(hsum2(add2(add2(b0,b1), add2(b2,b3))) + bb2);     \
      BCAST32(h2v);                                                            \
      const ulonglong2* _g = (const ulonglong2*)cur;                           \
      u64 c0=0,c1=0,d0=0,d1=0;                                                 \
      _Pragma("unroll")                                                        \
      for (int j = 0; j < 4; j++) {                                            \
          ulonglong2 qa = _g[2*j], qb = _g[2*j+1];                             \
          c0 = fma2(w3p0[4*j+0], qa.x, c0);                                    \
          c1 = fma2(w3p0[4*j+1], qa.y, c1);                                    \
          c0 = fma2(w3p0[4*j+2], qb.x, c0);                                    \
          c1 = fma2(w3p0[4*j+3], qb.y, c1);                                    \
          d0 = fma2(w3p1[4*j+0], qa.x, d0);                                    \
          d1 = fma2(w3p1[4*j+1], qa.y, d1);                                    \
          d0 = fma2(w3p1[4*j+2], qb.x, d0);                                    \
          d1 = fma2(w3p1[4*j+3], qb.y, d1);                                    \
      }                                                                        \
      float kx = hsum2(add2(c0, c1)) + b3x;                                    \
      float ky = hsum2(add2(d0, d1)) + b3y;                                    \
      (KP) = pk2(kx, ky);                                                      \
    } } while (0)

__global__ void __launch_bounds__(TPB)
ode_kernel(const float* __restrict__ x0s,
           const float* __restrict__ gW1, const float* __restrict__ gb1,
           const float* __restrict__ gW2, const float* __restrict__ gb2,
           const float* __restrict__ gW3, const float* __restrict__ gb3,
           const int*   __restrict__ Tp,
           float* __restrict__ out, int nTraj, int writeN)
{
    __shared__ __align__(16) float s_bufA[WPB][DIM];
    __shared__ __align__(16) float s_bufB[WPB][DIM];

    const int wi   = threadIdx.x >> 5;
    const int lane = threadIdx.x & 31;
    const int traj = blockIdx.x * WPB + wi;
    if (traj >= nTraj) return;

    float* bufA = s_bufA[wi];
    float* bufB = s_bufB[wi];
    int bsel = 0;
    const float* cur = bufA;

    // Weights: lane owns W1 row L, W2 row L, W3 rows 2L and 2L+1 (packed pairs).
    u64 w1p[32], w2p[16], w3p0[16], w3p1[16];
    {
        const u64* r1 = (const u64*)(gW1 + lane * DIM);
        #pragma unroll
        for (int j = 0; j < 32; j++) w1p[j] = __ldg(r1 + j);
        const u64* r2 = (const u64*)(gW2 + lane * HID);
        #pragma unroll
        for (int j = 0; j < 16; j++) w2p[j] = __ldg(r2 + j);
        const u64* r3a = (const u64*)(gW3 + (2*lane)   * HID);
        const u64* r3b = (const u64*)(gW3 + (2*lane+1) * HID);
        #pragma unroll
        for (int j = 0; j < 16; j++) { w3p0[j] = __ldg(r3a + j); w3p1[j] = __ldg(r3b + j); }
    }
    const float bb1 = __ldg(gb1 + lane);
    const float bb2 = __ldg(gb2 + lane);
    const float b3x = __ldg(gb3 + 2*lane);
    const float b3y = __ldg(gb3 + 2*lane + 1);

    u64 y = ((const u64*)(x0s + (size_t)traj * DIM))[lane];

    float* orow = out + (size_t)traj * (TRAJ_LEN * DIM);
    ((u64*)orow)[lane] = y;

    const float Tf   = (float)__ldg(Tp);
    const float step = Tf / 10.0f;
    float t  = 0.0f;
    float dt = 1e-3f;
    int   n  = 0;

    // FSAL: k1 = f(y). y only changes on accepted steps, where the new k1
    // equals the accepted step's k7 = f(y5) (bitwise, same input). So one
    // fresh eval here, then k1 is carried: reject -> unchanged, accept -> k7.
    u64 k1;
    FEVAL(y, k1);

    for (int iv = 1; iv < TRAJ_LEN; iv++) {
        const float t_target = step * (float)iv;

        for (int it = 0; it < MAXI; it++) {
            float remaining = t_target - t;
            if (remaining <= 1e-12f) break;   // ref freezes state when done: exact early-exit
            n++;

            float h = fminf(dt, fmaxf(remaining, 0.0f));

            u64 k2, k3, k4, k5, k6, k7, z;

            z = fma2(pkb(h*cA21), k1, y);
            FEVAL(z, k2);

            z = fma2(pkb(h*cA31), k1, fma2(pkb(h*cA32), k2, y));
            FEVAL(z, k3);

            z = fma2(pkb(h*cA41), k1, fma2(pkb(h*cA42), k2, fma2(pkb(h*cA43), k3, y)));
            FEVAL(z, k4);

            z = fma2(pkb(h*cA51), k1, fma2(pkb(h*cA52), k2, fma2(pkb(h*cA53), k3,
                fma2(pkb(h*cA54), k4, y))));
            FEVAL(z, k5);

            z = fma2(pkb(h*cA61), k1, fma2(pkb(h*cA62), k2, fma2(pkb(h*cA63), k3,
                fma2(pkb(h*cA64), k4, fma2(pkb(h*cA65), k5, y)))));
            FEVAL(z, k6);

            u64 y5 = fma2(pkb(h*cB1), k1, fma2(pkb(h*cB2), k2, fma2(pkb(h*cB3), k3,
                     fma2(pkb(h*cB4), k4, fma2(pkb(h*cB5), k5, fma2(pkb(h*cB6), k6, y))))));

            FEVAL(y5, k7);

            u64 err = fma2(pkb(h*cE1), k1, fma2(pkb(h*cE2), k2, fma2(pkb(h*cE3), k3,
                      fma2(pkb(h*cE4), k4, fma2(pkb(h*cE5), k5, fma2(pkb(h*cE6), k6,
                      mul2(pkb(h*cE7), k7)))))));

            float ylo, yhi, y5lo, y5hi, elo, ehi;
            upk(y, ylo, yhi); upk(y5, y5lo, y5hi); upk(err, elo, ehi);

            float sclo = fmaf(RTOL, fmaxf(fabsf(ylo), fabsf(y5lo)), ATOL);
            float schi = fmaf(RTOL, fmaxf(fabsf(yhi), fabsf(y5hi)), ATOL);
            float rlo = __fdividef(elo, sclo);
            float rhi = __fdividef(ehi, schi);
            float ss  = fmaf(rlo, rlo, rhi * rhi);
            #pragma unroll
            for (int o = 16; o; o >>= 1)
                ss += __shfl_xor_sync(0xffffffffu, ss, o);

            // accept: max(sqrt(ss/64),1e-10) <= 1  <=>  ss <= 64 (sqrt monotone)
            bool accept = (ss <= 64.0f);
            // fac = clip(0.9*enorm^-0.2, 0.1, 5); enorm^-0.2 = (ss/64)^-0.1
            float q   = fmaxf(ss * 0.015625f, 1e-20f);
            float fac = fminf(fmaxf(0.9f * __powf(q, -0.1f), 0.1f), 5.0f);

            if (accept) { t = t + h; y = y5; k1 = k7; }
            dt = fmaxf(h * fac, 1e-8f);
        }

        ((u64*)(orow + iv * DIM))[lane] = y;
    }

    if (writeN && lane == 0)
        atomicAdd(out + (size_t)nTraj * TRAJ_LEN * DIM, (float)n);
}

extern "C" void kernel_launch(void* const* d_in, const int* in_sizes, int n_in,
                              void* d_out, int out_size)
{
    const float* x0s = (const float*)d_in[0];
    const float* W1  = (const float*)d_in[1];
    const float* b1  = (const float*)d_in[2];
    const float* W2  = (const float*)d_in[3];
    const float* b2  = (const float*)d_in[4];
    const float* W3  = (const float*)d_in[5];
    const float* b3  = (const float*)d_in[6];
    const int*   T   = (const int*)  d_in[7];
    float* out = (float*)d_out;

    const int nTraj = in_sizes[0] / DIM;
    const int trajElems = nTraj * TRAJ_LEN * DIM;
    const int writeN = (out_size > trajElems) ? 1 : 0;

    if (writeN) {
        cudaMemsetAsync((char*)d_out + (size_t)trajElems * sizeof(float), 0,
                        (size_t)(out_size - trajElems) * sizeof(float), 0);
    }

    const int blocks = (nTraj + WPB - 1) / WPB;
    ode_kernel<<<blocks, TPB>>>(x0s, W1, b1, W2, b2, W3, b3, T, out, nTraj, writeN);
}

// round 9
// speedup vs baseline: 1.7358x; 1.0591x over previous
#include <cuda_runtime.h>
#include <math.h>

// ---------------------------------------------------------------------------
// NeuralODE Tsit5, TWO trajectories per warp (shared weight registers,
// interleaved independent chains), f32x2-packed, FSAL, LDS ping-pong.
// Lane L owns components (2L, 2L+1) of both trajectories.
// ---------------------------------------------------------------------------

#define DIM      64
#define HID      32
#define TRAJ_LEN 11
#define MAXI     64

typedef unsigned long long u64;

__device__ __forceinline__ u64 pk2(float lo, float hi) {
    u64 r; asm("mov.b64 %0,{%1,%2};" : "=l"(r) : "f"(lo), "f"(hi)); return r;
}
__device__ __forceinline__ u64 pkb(float x) { return pk2(x, x); }
__device__ __forceinline__ void upk(u64 v, float& a, float& b) {
    asm("mov.b64 {%0,%1},%2;" : "=f"(a), "=f"(b) : "l"(v));
}
__device__ __forceinline__ u64 fma2(u64 a, u64 b, u64 c) {
    u64 d; asm("fma.rn.f32x2 %0,%1,%2,%3;" : "=l"(d) : "l"(a), "l"(b), "l"(c)); return d;
}
__device__ __forceinline__ u64 add2(u64 a, u64 b) {
    u64 d; asm("add.rn.f32x2 %0,%1,%2;" : "=l"(d) : "l"(a), "l"(b)); return d;
}
__device__ __forceinline__ u64 mul2(u64 a, u64 b) {
    u64 d; asm("mul.rn.f32x2 %0,%1,%2;" : "=l"(d) : "l"(a), "l"(b)); return d;
}
__device__ __forceinline__ float hsum2(u64 v) { float a, b; upk(v, a, b); return a + b; }

// Tsit5 tableau (f32) — C_ namespace to avoid any identifier collision
#define C_A21 ((float)0.161)
#define C_A31 ((float)-0.008480655492356989)
#define C_A32 ((float)0.335480655492357)
#define C_A41 ((float)2.8971530571054935)
#define C_A42 ((float)-6.359448489975075)
#define C_A43 ((float)4.3622954328695815)
#define C_A51 ((float)5.325864828439257)
#define C_A52 ((float)-11.748883564062828)
#define C_A53 ((float)7.4955393428898365)
#define C_A54 ((float)-0.09249506636175525)
#define C_A61 ((float)5.86145544294642)
#define C_A62 ((float)-12.92096931784711)
#define C_A63 ((float)8.159367898576159)
#define C_A64 ((float)-0.071584973281401)
#define C_A65 ((float)-0.028269050394068383)
#define C_B1  ((float)0.09646076681806523)
#define C_B2  ((float)0.01)
#define C_B3  ((float)0.4798896504144996)
#define C_B4  ((float)1.379008574103742)
#define C_B5  ((float)-3.290069515436081)
#define C_B6  ((float)2.324710524099774)
#define C_E1  ((float)-0.00178001105222577714)
#define C_E2  ((float)-0.0008164344596567469)
#define C_E3  ((float)0.007880878010261995)
#define C_E4  ((float)-0.1447110071732629)
#define C_E5  ((float)0.5823571654525552)
#define C_E6  ((float)-0.45808210592918697)
#define C_E7  ((float)0.015151515151515152)

#define RTOL 1e-3f
#define ATOL 1e-6f

__device__ __forceinline__ float softplus_f(float x) {
    return fmaxf(x, 0.0f) + __logf(1.0f + __expf(-fabsf(x)));
}

// Dual ping-pong broadcast: both trajectories share ONE syncwarp.
#define BC64x2(ZA, ZB) do { bsel ^= 1;                                          \
    float* _ba = bsel ? bA0 : bA1; float* _bb = bsel ? bB0 : bB1;               \
    ((u64*)_ba)[lane] = (ZA); ((u64*)_bb)[lane] = (ZB);                         \
    __syncwarp(); curA = _ba; curB = _bb; } while (0)
#define BC32x2(HA, HB) do { bsel ^= 1;                                          \
    float* _ba = bsel ? bA0 : bA1; float* _bb = bsel ? bB0 : bB1;               \
    _ba[lane] = (HA); _bb[lane] = (HB);                                         \
    __syncwarp(); curA = _ba; curB = _bb; } while (0)

// Dual MLP eval: two independent chains interleaved for ILP.
#define FEVAL2(ZA, ZB, KA, KB) do {                                             \
    BC64x2(ZA, ZB);                                                             \
    { const ulonglong2* _zA = (const ulonglong2*)curA;                          \
      const ulonglong2* _zB = (const ulonglong2*)curB;                          \
      u64 _aA0=0,_aA1=0,_aA2=0,_aA3=0, _aB0=0,_aB1=0,_aB2=0,_aB3=0;             \
      _Pragma("unroll")                                                         \
      for (int _j = 0; _j < 8; _j++) {                                          \
          ulonglong2 _pA = _zA[2*_j], _rA = _zA[2*_j+1];                        \
          ulonglong2 _pB = _zB[2*_j], _rB = _zB[2*_j+1];                        \
          _aA0 = fma2(w1p[4*_j+0], _pA.x, _aA0);                                \
          _aB0 = fma2(w1p[4*_j+0], _pB.x, _aB0);                                \
          _aA1 = fma2(w1p[4*_j+1], _pA.y, _aA1);                                \
          _aB1 = fma2(w1p[4*_j+1], _pB.y, _aB1);                                \
          _aA2 = fma2(w1p[4*_j+2], _rA.x, _aA2);                                \
          _aB2 = fma2(w1p[4*_j+2], _rB.x, _aB2);                                \
          _aA3 = fma2(w1p[4*_j+3], _rA.y, _aA3);                                \
          _aB3 = fma2(w1p[4*_j+3], _rB.y, _aB3);                                \
      }                                                                         \
      float _h1A = softplus_f(hsum2(add2(add2(_aA0,_aA1), add2(_aA2,_aA3))) + bb1); \
      float _h1B = softplus_f(hsum2(add2(add2(_aB0,_aB1), add2(_aB2,_aB3))) + bb1); \
      BC32x2(_h1A, _h1B);                                                       \
      const ulonglong2* _hA = (const ulonglong2*)curA;                          \
      const ulonglong2* _hB = (const ulonglong2*)curB;                          \
      u64 _sA0=0,_sA1=0, _sB0=0,_sB1=0;                                         \
      _Pragma("unroll")                                                         \
      for (int _j = 0; _j < 4; _j++) {                                          \
          ulonglong2 _qA = _hA[2*_j], _gA = _hA[2*_j+1];                        \
          ulonglong2 _qB = _hB[2*_j], _gB = _hB[2*_j+1];                        \
          _sA0 = fma2(w2p[4*_j+0], _qA.x, _sA0);                                \
          _sB0 = fma2(w2p[4*_j+0], _qB.x, _sB0);                                \
          _sA1 = fma2(w2p[4*_j+1], _qA.y, _sA1);                                \
          _sB1 = fma2(w2p[4*_j+1], _qB.y, _sB1);                                \
          _sA0 = fma2(w2p[4*_j+2], _gA.x, _sA0);                                \
          _sB0 = fma2(w2p[4*_j+2], _gB.x, _sB0);                                \
          _sA1 = fma2(w2p[4*_j+3], _gA.y, _sA1);                                \
          _sB1 = fma2(w2p[4*_j+3], _gB.y, _sB1);                                \
      }                                                                         \
      float _h2A = softplus_f(hsum2(add2(_sA0,_sA1)) + bb2);                    \
      float _h2B = softplus_f(hsum2(add2(_sB0,_sB1)) + bb2);                    \
      BC32x2(_h2A, _h2B);                                                       \
      const ulonglong2* _gpA = (const ulonglong2*)curA;                         \
      const ulonglong2* _gpB = (const ulonglong2*)curB;                         \
      u64 _cA0=0,_cA1=0,_dA0=0,_dA1=0, _cB0=0,_cB1=0,_dB0=0,_dB1=0;             \
      _Pragma("unroll")                                                         \
      for (int _j = 0; _j < 4; _j++) {                                          \
          ulonglong2 _qA = _gpA[2*_j], _gA = _gpA[2*_j+1];                      \
          ulonglong2 _qB = _gpB[2*_j], _gB = _gpB[2*_j+1];                      \
          _cA0 = fma2(w3p0[4*_j+0], _qA.x, _cA0);                               \
          _cB0 = fma2(w3p0[4*_j+0], _qB.x, _cB0);                               \
          _cA1 = fma2(w3p0[4*_j+1], _qA.y, _cA1);                               \
          _cB1 = fma2(w3p0[4*_j+1], _qB.y, _cB1);                               \
          _cA0 = fma2(w3p0[4*_j+2], _gA.x, _cA0);                               \
          _cB0 = fma2(w3p0[4*_j+2], _gB.x, _cB0);                               \
          _cA1 = fma2(w3p0[4*_j+3], _gA.y, _cA1);                               \
          _cB1 = fma2(w3p0[4*_j+3], _gB.y, _cB1);                               \
          _dA0 = fma2(w3p1[4*_j+0], _qA.x, _dA0);                               \
          _dB0 = fma2(w3p1[4*_j+0], _qB.x, _dB0);                               \
          _dA1 = fma2(w3p1[4*_j+1], _qA.y, _dA1);                               \
          _dB1 = fma2(w3p1[4*_j+1], _qB.y, _dB1);                               \
          _dA0 = fma2(w3p1[4*_j+2], _gA.x, _dA0);                               \
          _dB0 = fma2(w3p1[4*_j+2], _gB.x, _dB0);                               \
          _dA1 = fma2(w3p1[4*_j+3], _gA.y, _dA1);                               \
          _dB1 = fma2(w3p1[4*_j+3], _gB.y, _dB1);                               \
      }                                                                         \
      (KA) = pk2(hsum2(add2(_cA0,_cA1)) + b3x, hsum2(add2(_dA0,_dA1)) + b3y);   \
      (KB) = pk2(hsum2(add2(_cB0,_cB1)) + b3x, hsum2(add2(_dB0,_dB1)) + b3y);   \
    } } while (0)

__global__ void __launch_bounds__(32, 8)
ode_kernel(const float* __restrict__ x0s,
           const float* __restrict__ gW1, const float* __restrict__ gb1,
           const float* __restrict__ gW2, const float* __restrict__ gb2,
           const float* __restrict__ gW3, const float* __restrict__ gb3,
           const int*   __restrict__ Tp,
           float* __restrict__ out, int nTraj, int writeN)
{
    __shared__ __align__(16) float bA0[DIM], bA1[DIM], bB0[DIM], bB1[DIM];

    const int lane  = threadIdx.x & 31;
    const int trajA = blockIdx.x * 2;
    const int trajB = trajA + 1;
    if (trajA >= nTraj) return;
    const bool hasB = (trajB < nTraj);

    int bsel = 0;
    const float* curA = bA0;
    const float* curB = bB0;

    // Shared weight registers: lane owns W1 row L, W2 row L, W3 rows 2L, 2L+1.
    u64 w1p[32], w2p[16], w3p0[16], w3p1[16];
    {
        const u64* r1 = (const u64*)(gW1 + lane * DIM);
        #pragma unroll
        for (int j = 0; j < 32; j++) w1p[j] = __ldg(r1 + j);
        const u64* r2 = (const u64*)(gW2 + lane * HID);
        #pragma unroll
        for (int j = 0; j < 16; j++) w2p[j] = __ldg(r2 + j);
        const u64* r3a = (const u64*)(gW3 + (2*lane)   * HID);
        const u64* r3b = (const u64*)(gW3 + (2*lane+1) * HID);
        #pragma unroll
        for (int j = 0; j < 16; j++) { w3p0[j] = __ldg(r3a + j); w3p1[j] = __ldg(r3b + j); }
    }
    const float bb1 = __ldg(gb1 + lane);
    const float bb2 = __ldg(gb2 + lane);
    const float b3x = __ldg(gb3 + 2*lane);
    const float b3y = __ldg(gb3 + 2*lane + 1);

    u64 yA = ((const u64*)(x0s + (size_t)trajA * DIM))[lane];
    u64 yB = hasB ? ((const u64*)(x0s + (size_t)trajB * DIM))[lane] : yA;

    float* orowA = out + (size_t)trajA * (TRAJ_LEN * DIM);
    float* orowB = out + (size_t)trajB * (TRAJ_LEN * DIM);
    ((u64*)orowA)[lane] = yA;
    if (hasB) ((u64*)orowB)[lane] = yB;

    const float Tf   = (float)__ldg(Tp);
    const float step = Tf / 10.0f;
    float tA = 0.0f, tB = 0.0f;
    float dtA = 1e-3f, dtB = 1e-3f;
    int   nA = 0, nB = 0;

    // FSAL seed
    u64 k1A, k1B;
    FEVAL2(yA, yB, k1A, k1B);

    for (int iv = 1; iv < TRAJ_LEN; iv++) {
        const float t_target = step * (float)iv;

        for (int it = 0; it < MAXI; it++) {
            float remA = t_target - tA;
            float remB = t_target - tB;
            bool doneA = (remA <= 1e-12f);
            bool doneB = (remB <= 1e-12f);
            if (doneA && doneB) break;          // ref freezes state when done: exact
            nA += doneA ? 0 : 1;
            nB += doneB ? 0 : 1;

            float hA = fminf(dtA, fmaxf(remA, 0.0f));
            float hB = fminf(dtB, fmaxf(remB, 0.0f));

            u64 k2A,k3A,k4A,k5A,k6A,k7A, k2B,k3B,k4B,k5B,k6B,k7B, zA, zB;

            zA = fma2(pkb(hA*C_A21), k1A, yA);
            zB = fma2(pkb(hB*C_A21), k1B, yB);
            FEVAL2(zA, zB, k2A, k2B);

            zA = fma2(pkb(hA*C_A31), k1A, fma2(pkb(hA*C_A32), k2A, yA));
            zB = fma2(pkb(hB*C_A31), k1B, fma2(pkb(hB*C_A32), k2B, yB));
            FEVAL2(zA, zB, k3A, k3B);

            zA = fma2(pkb(hA*C_A41), k1A, fma2(pkb(hA*C_A42), k2A, fma2(pkb(hA*C_A43), k3A, yA)));
            zB = fma2(pkb(hB*C_A41), k1B, fma2(pkb(hB*C_A42), k2B, fma2(pkb(hB*C_A43), k3B, yB)));
            FEVAL2(zA, zB, k4A, k4B);

            zA = fma2(pkb(hA*C_A51), k1A, fma2(pkb(hA*C_A52), k2A, fma2(pkb(hA*C_A53), k3A,
                 fma2(pkb(hA*C_A54), k4A, yA))));
            zB = fma2(pkb(hB*C_A51), k1B, fma2(pkb(hB*C_A52), k2B, fma2(pkb(hB*C_A53), k3B,
                 fma2(pkb(hB*C_A54), k4B, yB))));
            FEVAL2(zA, zB, k5A, k5B);

            zA = fma2(pkb(hA*C_A61), k1A, fma2(pkb(hA*C_A62), k2A, fma2(pkb(hA*C_A63), k3A,
                 fma2(pkb(hA*C_A64), k4A, fma2(pkb(hA*C_A65), k5A, yA)))));
            zB = fma2(pkb(hB*C_A61), k1B, fma2(pkb(hB*C_A62), k2B, fma2(pkb(hB*C_A63), k3B,
                 fma2(pkb(hB*C_A64), k4B, fma2(pkb(hB*C_A65), k5B, yB)))));
            FEVAL2(zA, zB, k6A, k6B);

            u64 y5A = fma2(pkb(hA*C_B1), k1A, fma2(pkb(hA*C_B2), k2A, fma2(pkb(hA*C_B3), k3A,
                      fma2(pkb(hA*C_B4), k4A, fma2(pkb(hA*C_B5), k5A, fma2(pkb(hA*C_B6), k6A, yA))))));
            u64 y5B = fma2(pkb(hB*C_B1), k1B, fma2(pkb(hB*C_B2), k2B, fma2(pkb(hB*C_B3), k3B,
                      fma2(pkb(hB*C_B4), k4B, fma2(pkb(hB*C_B5), k5B, fma2(pkb(hB*C_B6), k6B, yB))))));

            FEVAL2(y5A, y5B, k7A, k7B);

            u64 errA = fma2(pkb(hA*C_E1), k1A, fma2(pkb(hA*C_E2), k2A, fma2(pkb(hA*C_E3), k3A,
                       fma2(pkb(hA*C_E4), k4A, fma2(pkb(hA*C_E5), k5A, fma2(pkb(hA*C_E6), k6A,
                       mul2(pkb(hA*C_E7), k7A)))))));
            u64 errB = fma2(pkb(hB*C_E1), k1B, fma2(pkb(hB*C_E2), k2B, fma2(pkb(hB*C_E3), k3B,
                       fma2(pkb(hB*C_E4), k4B, fma2(pkb(hB*C_E5), k5B, fma2(pkb(hB*C_E6), k6B,
                       mul2(pkb(hB*C_E7), k7B)))))));

            float ylo, yhi, y5lo, y5hi, elo, ehi;
            upk(yA, ylo, yhi); upk(y5A, y5lo, y5hi); upk(errA, elo, ehi);
            float sclo = fmaf(RTOL, fmaxf(fabsf(ylo), fabsf(y5lo)), ATOL);
            float schi = fmaf(RTOL, fmaxf(fabsf(yhi), fabsf(y5hi)), ATOL);
            float rlo = __fdividef(elo, sclo);
            float rhi = __fdividef(ehi, schi);
            float ssA = fmaf(rlo, rlo, rhi * rhi);

            upk(yB, ylo, yhi); upk(y5B, y5lo, y5hi); upk(errB, elo, ehi);
            sclo = fmaf(RTOL, fmaxf(fabsf(ylo), fabsf(y5lo)), ATOL);
            schi = fmaf(RTOL, fmaxf(fabsf(yhi), fabsf(y5hi)), ATOL);
            rlo = __fdividef(elo, sclo);
            rhi = __fdividef(ehi, schi);
            float ssB = fmaf(rlo, rlo, rhi * rhi);

            #pragma unroll
            for (int o = 16; o; o >>= 1) {
                ssA += __shfl_xor_sync(0xffffffffu, ssA, o);
                ssB += __shfl_xor_sync(0xffffffffu, ssB, o);
            }

            bool acceptA = (ssA <= 64.0f);      // == (max(sqrt(ss/64),1e-10) <= 1)
            bool acceptB = (ssB <= 64.0f);
            float qA = fmaxf(ssA * 0.015625f, 1e-20f);
            float qB = fmaxf(ssB * 0.015625f, 1e-20f);
            float facA = fminf(fmaxf(0.9f * __powf(qA, -0.1f), 0.1f), 5.0f);
            float facB = fminf(fmaxf(0.9f * __powf(qB, -0.1f), 0.1f), 5.0f);

            if (!doneA) {
                if (acceptA) { tA += hA; yA = y5A; k1A = k7A; }
                dtA = fmaxf(hA * facA, 1e-8f);
            }
            if (!doneB) {
                if (acceptB) { tB += hB; yB = y5B; k1B = k7B; }
                dtB = fmaxf(hB * facB, 1e-8f);
            }
        }

        ((u64*)(orowA + iv * DIM))[lane] = yA;
        if (hasB) ((u64*)(orowB + iv * DIM))[lane] = yB;
    }

    if (writeN && lane == 0)
        atomicAdd(out + (size_t)nTraj * TRAJ_LEN * DIM, (float)(nA + (hasB ? nB : 0)));
}

extern "C" void kernel_launch(void* const* d_in, const int* in_sizes, int n_in,
                              void* d_out, int out_size)
{
    const float* x0s = (const float*)d_in[0];
    const float* W1  = (const float*)d_in[1];
    const float* b1  = (const float*)d_in[2];
    const float* W2  = (const float*)d_in[3];
    const float* b2  = (const float*)d_in[4];
    const float* W3  = (const float*)d_in[5];
    const float* b3  = (const float*)d_in[6];
    const int*   T   = (const int*)  d_in[7];
    float* out = (float*)d_out;

    const int nTraj = in_sizes[0] / DIM;
    const int trajElems = nTraj * TRAJ_LEN * DIM;
    const int writeN = (out_size > trajElems) ? 1 : 0;

    if (writeN) {
        cudaMemsetAsync((char*)d_out + (size_t)trajElems * sizeof(float), 0,
                        (size_t)(out_size - trajElems) * sizeof(float), 0);
    }

    const int nPair = (nTraj + 1) / 2;
    ode_kernel<<<nPair, 32>>>(x0s, W1, b1, W2, b2, W3, b3, T, out, nTraj, writeN);
}